// round 5
// baseline (speedup 1.0000x reference)
#include <cuda_runtime.h>
#include <cstdint>

// Problem constants (fixed for this problem instance)
#define B_DIM 4096
#define F_DIM 16384
#define G_DIM 512
#define S_DIM 32
#define N_IDX (G_DIM * S_DIM)   // 16384 indices

// Scratch: folded per-feature weight pw[f] = sum_{j: idx[j]==f} w_group[j]*fc_kernel[j/S].
// 64 KB, hot in L2 during the main pass.
__device__ float g_pw[F_DIM];
__device__ int   g_idx_is64;   // 1 if group_idx buffer is int64, 0 if int32

__global__ void zero_pw_kernel() {
    int i = blockIdx.x * blockDim.x + threadIdx.x;
    if (i < F_DIM) g_pw[i] = 0.0f;
}

// Detect index dtype from raw 32-bit words. int64 little-endian with values
// < 2^31 has every odd 32-bit word == 0; int32 indices (any nontrivial set)
// have nonzero values at odd word positions. Reads only the first 64 words,
// which is in-bounds for either interpretation (int32 buffer: 16384 words).
__global__ void detect_idx_kernel(const unsigned int* __restrict__ idx_words) {
    int is64 = 1;
    #pragma unroll
    for (int j = 0; j < 32; j++) {
        if (idx_words[2 * j + 1] != 0u) { is64 = 0; break; }
    }
    g_idx_is64 = is64;
}

__global__ void scatter_weights_kernel(const void* __restrict__ group_idx,
                                       const float* __restrict__ w_group,
                                       const float* __restrict__ fc_kernel) {
    int j = blockIdx.x * blockDim.x + threadIdx.x;  // j in [0, N_IDX)
    if (j < N_IDX) {
        int g = j / S_DIM;
        float w = w_group[j] * fc_kernel[g];  // UNITS == 1
        long long f;
        if (g_idx_is64) {
            f = ((const long long*)group_idx)[j];
        } else {
            f = (long long)((const int*)group_idx)[j];
        }
        if (f >= 0 && f < F_DIM) {
            atomicAdd(&g_pw[(int)f], w);
        }
    }
}

// One block per row b: out[b] = dot(x[b, :], pw).  Pure HBM stream of x.
__global__ void __launch_bounds__(256) row_dot_kernel(const float* __restrict__ x,
                                                      float* __restrict__ out) {
    const int b = blockIdx.x;
    const int tid = threadIdx.x;

    const float4* __restrict__ xr = reinterpret_cast<const float4*>(x + (size_t)b * F_DIM);
    const float4* __restrict__ pw = reinterpret_cast<const float4*>(g_pw);

    float acc = 0.0f;
    // F/4 = 4096 float4; 256 threads -> 16 iterations each
    #pragma unroll 16
    for (int i = tid; i < F_DIM / 4; i += 256) {
        float4 a = __ldcs(&xr[i]);   // streaming: x is read exactly once
        float4 w = __ldg(&pw[i]);    // pw is hot in L2/L1
        acc += a.x * w.x + a.y * w.y + a.z * w.z + a.w * w.w;
    }

    // Warp reduce
    #pragma unroll
    for (int off = 16; off > 0; off >>= 1)
        acc += __shfl_down_sync(0xFFFFFFFFu, acc, off);

    // Block reduce across 8 warps
    __shared__ float warp_sum[8];
    int wid = tid >> 5, lid = tid & 31;
    if (lid == 0) warp_sum[wid] = acc;
    __syncthreads();
    if (wid == 0) {
        float v = (lid < 8) ? warp_sum[lid] : 0.0f;
        #pragma unroll
        for (int off = 4; off > 0; off >>= 1)
            v += __shfl_down_sync(0xFFFFFFFFu, v, off);
        if (lid == 0) out[b] = v;
    }
}

extern "C" void kernel_launch(void* const* d_in, const int* in_sizes, int n_in,
                              void* d_out, int out_size) {
    const float* x         = (const float*)d_in[0];
    const void*  group_idx = d_in[1];
    const float* w_group   = (const float*)d_in[2];
    const float* fc_kernel = (const float*)d_in[3];
    float* out = (float*)d_out;

    zero_pw_kernel<<<(F_DIM + 255) / 256, 256>>>();
    detect_idx_kernel<<<1, 1>>>((const unsigned int*)group_idx);
    scatter_weights_kernel<<<(N_IDX + 255) / 256, 256>>>(group_idx, w_group, fc_kernel);
    row_dot_kernel<<<B_DIM, 256>>>(x, out);
}